// round 13
// baseline (speedup 1.0000x reference)
#include <cuda_runtime.h>

#define NW      18
#define DIM     (1 << 18)
#define BATCH   64
#define THREADS 512
#define TILE    8192           // amplitudes per CTA tile (u64 re/im pair -> 64 KB smem)
#define NACC    14             // 13 masked sums (bits 0..12) + total prob
#define NSTAGE  6              // h0,l0,h1,l1,h2,l2
#define GRPB    8              // batches per locality group (L2-resident working set)
#define NTASK   (BATCH * NSTAGE * 32)
#define PGRID   296            // persistent grid = resident capacity (2 CTA/SM)

typedef unsigned long long u64;
typedef ulonglong2 u64x2;

// Ping-pong state buffers. h: reads input/g_b, writes g_a. l: reads g_a,
// writes g_b (S_L-permuted at write) or fused exp-val on the last stage.
__device__ __align__(16) u64 g_a[(size_t)BATCH * DIM];
__device__ __align__(16) u64 g_b[(size_t)BATCH * DIM];
__device__ float2 g_ry[3][NW];
__device__ u64    g_phz_h[3][256];
__device__ u64    g_phz_l[3][1024];
__device__ float  g_part[BATCH * 32 * NACC];
__device__ int    g_qhead;                  // task queue head
__device__ int    g_done[BATCH][NSTAGE];    // per-(b,stage) completed-chunk counts

// ---- packed f32x2 helpers ---------------------------------------------------
static __device__ __forceinline__ u64 pk2(float x, float y) {
    u64 r; asm("mov.b64 %0,{%1,%2};" : "=l"(r) : "f"(x), "f"(y)); return r;
}
static __device__ __forceinline__ void up2(u64 a, float& x, float& y) {
    asm("mov.b64 {%0,%1},%2;" : "=f"(x), "=f"(y) : "l"(a));
}
static __device__ __forceinline__ u64 fma2_(u64 a, u64 b, u64 c) {
    u64 r; asm("fma.rn.f32x2 %0,%1,%2,%3;" : "=l"(r) : "l"(a), "l"(b), "l"(c)); return r;
}
static __device__ __forceinline__ u64 mul2_(u64 a, u64 b) {
    u64 r; asm("mul.rn.f32x2 %0,%1,%2;" : "=l"(r) : "l"(a), "l"(b)); return r;
}

// ---------------------------------------------------------------------------
__global__ void prep_kernel(const float* __restrict__ params) {
    int t = threadIdx.x;
    if (t == 0) g_qhead = 0;
    if (t < BATCH * NSTAGE) ((int*)g_done)[t] = 0;
    if (t < 3 * NW) {
        int l = t / NW, w = t % NW;
        float cy, sy;
        sincosf(0.5f * params[l * 36 + w], &sy, &cy);
        g_ry[l][w] = make_float2(cy, sy);
    }
    for (int i = t; i < 3 * 256; i += blockDim.x) {
        int l = i >> 8, idx = i & 255;
        float A = 0.f;
        for (int j = 0; j < 8; j++)
            if (!((idx >> j) & 1)) A += params[l * 36 + NW + (7 - j)];
        float s, c; sincosf(A, &s, &c);
        g_phz_h[l][idx] = pk2(c, -s);
    }
    for (int i = t; i < 3 * 1024; i += blockDim.x) {
        int l = i >> 10, idx = i & 1023;
        float A = 0.f;
        for (int j = 0; j < 10; j++)
            if (!((idx >> j) & 1)) A += params[l * 36 + NW + (17 - j)];
        float s, c; sincosf(A, &s, &c);
        g_phz_l[l][idx] = pk2(c, -s);
    }
}

// RY on a register pair (A: bit=0, B: bit=1).
static __device__ __forceinline__ void rp2y(u64& A, u64& B, u64 cy2, u64 sy2, u64 msy2) {
    u64 nA = fma2_(cy2, A, mul2_(msy2, B));
    u64 nB = fma2_(sy2, A, mul2_(cy2,  B));
    A = nA; B = nB;
}
static __device__ __forceinline__ void shroty(u64& v, u64 cy2, u64 sgn2, int d) {
    float vx, vy; up2(v, vx, vy);
    float ox = __shfl_xor_sync(0xffffffffu, vx, d);
    float oy = __shfl_xor_sync(0xffffffffu, vy, d);
    v = fma2_(cy2, v, mul2_(sgn2, pk2(ox, oy)));
}
static __device__ __forceinline__ u64 cmulp(u64 v, u64 p) {
    float x, y, pc, ps; up2(v, x, y); up2(p, pc, ps);
    return pk2(fmaf(-y, ps, x * pc), fmaf(x, ps, y * pc));
}
static __device__ __forceinline__ void rotpairs(u64* vl, u64* vh, int stride, float2 W) {
    u64 c = pk2(W.x, W.x), s = pk2(W.y, W.y), m = pk2(-W.y, -W.y);
#pragma unroll
    for (int i = 0; i < 8; i++)
        if (!(i & stride)) {
            rp2y(vl[i], vl[i | stride], c, s, m);
            rp2y(vh[i], vh[i | stride], c, s, m);
        }
}
static __device__ __forceinline__ int swz(int e) { return e ^ (((e >> 5) & 15) << 1); }

// ---------------------------------------------------------------------------
// H tile: RYs on global bits 10..17 (wires 0..7) + deferred phase (layers 0,1).
static __device__ __forceinline__ void h_tile(
    u64* sm, const float* __restrict__ in_re, const float* __restrict__ in_im,
    int layer, int b, int chunk)
{
    const int t = threadIdx.x, lane = t & 31, wrp = t >> 5;
    const size_t base = (size_t)b * DIM;

    if (layer == 0) {
#pragma unroll
        for (int i = 0; i < 4; i++) {
            int e4 = (i * THREADS + t) * 4;
            int a = (e4 & 31) | (chunk << 5) | ((e4 >> 5) << 10);
            float4 r4 = *(const float4*)(in_re + base + a);
            float4 i4 = *(const float4*)(in_im + base + a);
            int s0 = swz(e4);
            u64x2 p0; p0.x = pk2(r4.x, i4.x); p0.y = pk2(r4.y, i4.y);
            u64x2 p1; p1.x = pk2(r4.z, i4.z); p1.y = pk2(r4.w, i4.w);
            *(u64x2*)&sm[s0]     = p0;
            *(u64x2*)&sm[s0 ^ 2] = p1;
        }
    } else {
#pragma unroll
        for (int i = 0; i < 8; i++) {
            int e = (i * THREADS + t) * 2;
            int a = (e & 31) | (chunk << 5) | ((e >> 5) << 10);
            *(u64x2*)&sm[swz(e)] = *(const u64x2*)&g_b[base + a];
        }
    }
    __syncthreads();

    u64 vl[8], vh[8];
#pragma unroll
    for (int r = 0; r < 8; r++) {
        u64x2 p = *(u64x2*)&sm[swz((wrp << 1) | (lane << 5) | (r << 10))];
        vl[r] = p.x; vh[r] = p.y;
    }
#pragma unroll
    for (int q = 0; q < 5; q++) {
        float2 W = g_ry[layer][7 - q];
        float sgn = ((lane >> q) & 1) ? W.y : -W.y;
        u64 cy2 = pk2(W.x, W.x), sgn2 = pk2(sgn, sgn);
#pragma unroll
        for (int r = 0; r < 8; r++) { shroty(vl[r], cy2, sgn2, 1 << q); shroty(vh[r], cy2, sgn2, 1 << q); }
    }
    rotpairs(vl, vh, 1, g_ry[layer][2]);
    rotpairs(vl, vh, 2, g_ry[layer][1]);
    rotpairs(vl, vh, 4, g_ry[layer][0]);
    if (layer != 2) {
#pragma unroll
        for (int r = 0; r < 8; r++) {
            u64 ph = g_phz_h[layer][lane | (r << 5)];
            vl[r] = cmulp(vl[r], ph); vh[r] = cmulp(vh[r], ph);
        }
    }
#pragma unroll
    for (int r = 0; r < 8; r++) {
        u64x2 p; p.x = vl[r]; p.y = vh[r];
        *(u64x2*)&sm[swz((wrp << 1) | (lane << 5) | (r << 10))] = p;
    }
    __syncthreads();

#pragma unroll
    for (int i = 0; i < 8; i++) {
        int e = (i * THREADS + t) * 2;
        u64x2 p = *(u64x2*)&sm[swz(e)];
        int a = (e & 31) | (chunk << 5) | ((e >> 5) << 10);
        *(u64x2*)&g_a[base + a] = p;
    }
}

// ---------------------------------------------------------------------------
// L tile: RYs on global bits 0..9 (wires 17..8) + deferred phase; write-side
// S_L permutation (quad gather) or fused exp-val on the last stage.
static __device__ __forceinline__ void l_tile(u64* sm, int layer, int last, int b, int chunk)
{
    const int t = threadIdx.x, lane = t & 31, wrp = t >> 5;
    const size_t base = (size_t)b * DIM;

    u64 vl[8], vh[8];
#pragma unroll
    for (int r = 0; r < 8; r++) {
        int e = (wrp << 9) | (r << 6) | (lane << 1);
        int a = (chunk << 13) | e;
        a ^= (a >> 1) & 0x1F000;
        u64x2 p = *(const u64x2*)&g_a[base + a];
        vl[r] = p.x; vh[r] = p.y;
    }
    {
        float2 W = g_ry[layer][17];
        u64 c = pk2(W.x, W.x), s = pk2(W.y, W.y), m = pk2(-W.y, -W.y);
#pragma unroll
        for (int r = 0; r < 8; r++) rp2y(vl[r], vh[r], c, s, m);
    }
#pragma unroll
    for (int q = 0; q < 5; q++) {
        float2 W = g_ry[layer][16 - q];
        float sgn = ((lane >> q) & 1) ? W.y : -W.y;
        u64 cy2 = pk2(W.x, W.x), sgn2 = pk2(sgn, sgn);
#pragma unroll
        for (int r = 0; r < 8; r++) { shroty(vl[r], cy2, sgn2, 1 << q); shroty(vh[r], cy2, sgn2, 1 << q); }
    }
    rotpairs(vl, vh, 1, g_ry[layer][11]);
    rotpairs(vl, vh, 2, g_ry[layer][10]);
    rotpairs(vl, vh, 4, g_ry[layer][9]);
#pragma unroll
    for (int r = 0; r < 8; r++) {
        u64x2 p; p.x = vl[r]; p.y = vh[r];
        *(u64x2*)&sm[(wrp << 9) | (r << 6) | (lane << 1)] = p;
    }
    __syncthreads();

    float2 W8 = g_ry[layer][8];
    const u64 c8 = pk2(W8.x, W8.x), s8 = pk2(W8.y, W8.y), m8 = pk2(-W8.y, -W8.y);

    if (!last) {
#pragma unroll
        for (int u = 0; u < 4; u++) {
            int j  = (lane << 1) | (u << 6) | ((wrp & 1) << 8) | ((wrp >> 1) << 10);
            int k0 = j ^ ((j >> 1) & 0xFFF);
            int sw = k0 & 1;
            int bA = k0 & ~513;
            u64x2 pA = *(u64x2*)&sm[bA];
            u64x2 pB = *(u64x2*)&sm[bA | 512];
            u64 a0 = sw ? pA.y : pA.x, a1 = sw ? pA.x : pA.y;
            u64 b0v = sw ? pB.y : pB.x, b1 = sw ? pB.x : pB.y;
            rp2y(a0, b0v, c8, s8, m8);
            rp2y(a1, b1, c8, s8, m8);
            int hi9 = k0 & 512;
            u64 f00 = hi9 ? b0v : a0;
            u64 f01 = hi9 ? b1 : a1;
            u64 f10 = hi9 ? a0 : b0v;
            u64 f11 = hi9 ? a1 : b1;
            int kx = k0 & 1023;
            u64x2 W1, W2;
            W1.x = cmulp(f00, g_phz_l[layer][kx]);
            W1.y = cmulp(f01, g_phz_l[layer][kx ^ 1]);
            W2.x = cmulp(f11, g_phz_l[layer][kx ^ 513]);
            W2.y = cmulp(f10, g_phz_l[layer][kx ^ 512]);
            *(u64x2*)&g_b[base + (size_t)((chunk << 13) | j)] = W1;
            *(u64x2*)&g_b[base + (size_t)((chunk << 13) | (j ^ 0x3FE))] = W2;
        }
    } else {
        u64 wl[8], wh[8];
        const int e2b = (lane << 1) | ((wrp & 7) << 6) | ((wrp >> 3) << 10);
#pragma unroll
        for (int r = 0; r < 8; r++) {
            int e2 = e2b | ((r & 1) << 9) | (((r >> 1) & 1) << 11) | (((r >> 2) & 1) << 12);
            u64x2 p = *(u64x2*)&sm[e2];
            wl[r] = p.x; wh[r] = p.y;
        }
#pragma unroll
        for (int i = 0; i < 8; i += 2) { rp2y(wl[i], wl[i | 1], c8, s8, m8); rp2y(wh[i], wh[i | 1], c8, s8, m8); }

        float acc[NACC];
#pragma unroll
        for (int i = 0; i < NACC; i++) acc[i] = 0.f;
#pragma unroll
        for (int r = 0; r < 8; r++) {
            int e2 = e2b | ((r & 1) << 9) | (((r >> 1) & 1) << 11) | (((r >> 2) & 1) << 12);
            float lx, ly, hx, hy;
            up2(wl[r], lx, ly); up2(wh[r], hx, hy);
            float prl = lx * lx + ly * ly;
            float prh = hx * hx + hy * hy;
            float sum = prl + prh, dif = prl - prh;
            int p = e2;
            p ^= p >> 1; p ^= p >> 2; p ^= p >> 4; p ^= p >> 8;
            acc[0] += (p & 1) ? -dif : dif;
#pragma unroll
            for (int k = 1; k < 13; k++)
                acc[k] += ((p >> k) & 1) ? -sum : sum;
            acc[13] += sum;
        }
#pragma unroll
        for (int i = 0; i < NACC; i++)
#pragma unroll
            for (int o = 16; o > 0; o >>= 1)
                acc[i] += __shfl_xor_sync(0xffffffffu, acc[i], o);
        __syncthreads();
        float* red = (float*)sm;
        if (lane == 0)
#pragma unroll
            for (int i = 0; i < NACC; i++) red[wrp * NACC + i] = acc[i];
        __syncthreads();
        if (t < NACC) {
            float s = 0.f;
            for (int w2 = 0; w2 < 16; w2++) s += red[w2 * NACC + t];
            g_part[(b * 32 + chunk) * NACC + t] = s;
        }
    }
}

// ---------------------------------------------------------------------------
// Persistent work-stealing pipeline. Task order: (group of 8 b's) x stage x
// (b-in-group x chunk). One (group,stage) block = 256 tasks ~ chip capacity;
// dependencies are per-batch soft flags, so stage/group boundaries overlap
// instead of hard-barriering, and each group's ping-pong set stays in L2.
__global__ __launch_bounds__(THREADS, 2)
void circuit_kernel(const float* __restrict__ in_re, const float* __restrict__ in_im) {
    extern __shared__ u64 sm[];
    __shared__ int s_task;

    for (;;) {
        if (threadIdx.x == 0) s_task = atomicAdd(&g_qhead, 1);
        __syncthreads();
        const int i = s_task;
        if (i >= NTASK) return;

        const int gs    = i >> 8;            // (group, stage)
        const int g     = gs / NSTAGE;
        const int s     = gs % NSTAGE;
        const int j     = i & 255;
        const int b     = (g << 3) | (j >> 5);
        const int chunk = j & 31;
        const int layer = s >> 1;

        if (threadIdx.x == 0 && s > 0) {
            while (atomicAdd(&g_done[b][s - 1], 0) < 32) __nanosleep(128);
            __threadfence();                 // acquire: order tile reads after flag
        }
        __syncthreads();

        if (!(s & 1)) h_tile(sm, in_re, in_im, layer, b, chunk);
        else          l_tile(sm, layer, s == 5, b, chunk);
        __syncthreads();

        if (threadIdx.x == 0) {
            __threadfence();                 // release: publish tile writes
            atomicAdd(&g_done[b][s], 1);
        }
    }
}

// ---------------------------------------------------------------------------
__global__ void head_kernel(const float* __restrict__ head_w,
                            const float* __restrict__ head_b,
                            float* __restrict__ out) {
    int b = threadIdx.x;
    if (b >= BATCH) return;
    float fw[NW];
#pragma unroll
    for (int w = 0; w < NW; w++) fw[w] = 0.f;
    for (int c = 0; c < 32; c++) {
        const float* pp = &g_part[(b * 32 + c) * NACC];
#pragma unroll
        for (int k = 0; k < 13; k++) fw[17 - k] += pp[k];
        float sp = pp[13];
#pragma unroll
        for (int k = 13; k < 18; k++)
            fw[17 - k] += ((c >> (k - 13)) & 1) ? -sp : sp;
    }
    float o = head_b[0];
#pragma unroll
    for (int w = 0; w < NW; w++) o += fw[w] * head_w[w];
    out[b] = o;
}

// ---------------------------------------------------------------------------
extern "C" void kernel_launch(void* const* d_in, const int* in_sizes, int n_in,
                              void* d_out, int out_size) {
    const float* state_re = (const float*)d_in[0];
    const float* state_im = (const float*)d_in[1];
    const float* params   = (const float*)d_in[2];
    const float* head_w   = (const float*)d_in[3];
    const float* head_b   = (const float*)d_in[4];
    float* out = (float*)d_out;

    const int smem = TILE * sizeof(u64);   // 64 KB
    cudaFuncSetAttribute(circuit_kernel, cudaFuncAttributeMaxDynamicSharedMemorySize, smem);

    prep_kernel<<<1, 1024>>>(params);
    circuit_kernel<<<PGRID, THREADS, smem>>>(state_re, state_im);
    head_kernel<<<1, BATCH>>>(head_w, head_b, out);
}

// round 14
// speedup vs baseline: 1.1910x; 1.1910x over previous
#include <cuda_runtime.h>

#define NW      18
#define DIM     (1 << 18)
#define BATCH   64
#define THREADS 512
#define TILE    8192           // amplitudes per CTA tile (u64 re/im pair -> 64 KB smem)
#define NACC    14             // 13 masked sums (bits 0..12) + total prob
#define NSTAGE  6              // h0,l0,h1,l1,h2,l2
#define TPS     (BATCH * 32)   // tasks per stage (2048)
#define NTASK   (NSTAGE * TPS)
#define PGRID   296            // persistent grid = resident capacity (2 CTA/SM)

typedef unsigned long long u64;
typedef ulonglong2 u64x2;

// Ping-pong state buffers. h: reads input/g_b, writes g_a. l: reads g_a,
// writes g_b (S_L-permuted at write) or fused exp-val on the last stage.
__device__ __align__(16) u64 g_a[(size_t)BATCH * DIM];
__device__ __align__(16) u64 g_b[(size_t)BATCH * DIM];
__device__ float2 g_ry[3][NW];
__device__ u64    g_phz_h[3][256];
__device__ u64    g_phz_l[3][1024];
__device__ float  g_part[BATCH * 32 * NACC];
__device__ int    g_qhead;                  // task queue head
__device__ int    g_done[BATCH][NSTAGE];    // per-(b,stage) completed-chunk counts

// ---- packed f32x2 helpers ---------------------------------------------------
static __device__ __forceinline__ u64 pk2(float x, float y) {
    u64 r; asm("mov.b64 %0,{%1,%2};" : "=l"(r) : "f"(x), "f"(y)); return r;
}
static __device__ __forceinline__ void up2(u64 a, float& x, float& y) {
    asm("mov.b64 {%0,%1},%2;" : "=f"(x), "=f"(y) : "l"(a));
}
static __device__ __forceinline__ u64 fma2_(u64 a, u64 b, u64 c) {
    u64 r; asm("fma.rn.f32x2 %0,%1,%2,%3;" : "=l"(r) : "l"(a), "l"(b), "l"(c)); return r;
}
static __device__ __forceinline__ u64 mul2_(u64 a, u64 b) {
    u64 r; asm("mul.rn.f32x2 %0,%1,%2;" : "=l"(r) : "l"(a), "l"(b)); return r;
}

// ---------------------------------------------------------------------------
__global__ void prep_kernel(const float* __restrict__ params) {
    int t = threadIdx.x;
    if (t == 0) g_qhead = 0;
    if (t < BATCH * NSTAGE) ((int*)g_done)[t] = 0;
    if (t < 3 * NW) {
        int l = t / NW, w = t % NW;
        float cy, sy;
        sincosf(0.5f * params[l * 36 + w], &sy, &cy);
        g_ry[l][w] = make_float2(cy, sy);
    }
    for (int i = t; i < 3 * 256; i += blockDim.x) {
        int l = i >> 8, idx = i & 255;
        float A = 0.f;
        for (int j = 0; j < 8; j++)
            if (!((idx >> j) & 1)) A += params[l * 36 + NW + (7 - j)];
        float s, c; sincosf(A, &s, &c);
        g_phz_h[l][idx] = pk2(c, -s);
    }
    for (int i = t; i < 3 * 1024; i += blockDim.x) {
        int l = i >> 10, idx = i & 1023;
        float A = 0.f;
        for (int j = 0; j < 10; j++)
            if (!((idx >> j) & 1)) A += params[l * 36 + NW + (17 - j)];
        float s, c; sincosf(A, &s, &c);
        g_phz_l[l][idx] = pk2(c, -s);
    }
}

// RY on a register pair (A: bit=0, B: bit=1).
static __device__ __forceinline__ void rp2y(u64& A, u64& B, u64 cy2, u64 sy2, u64 msy2) {
    u64 nA = fma2_(cy2, A, mul2_(msy2, B));
    u64 nB = fma2_(sy2, A, mul2_(cy2,  B));
    A = nA; B = nB;
}
static __device__ __forceinline__ void shroty(u64& v, u64 cy2, u64 sgn2, int d) {
    float vx, vy; up2(v, vx, vy);
    float ox = __shfl_xor_sync(0xffffffffu, vx, d);
    float oy = __shfl_xor_sync(0xffffffffu, vy, d);
    v = fma2_(cy2, v, mul2_(sgn2, pk2(ox, oy)));
}
static __device__ __forceinline__ u64 cmulp(u64 v, u64 p) {
    float x, y, pc, ps; up2(v, x, y); up2(p, pc, ps);
    return pk2(fmaf(-y, ps, x * pc), fmaf(x, ps, y * pc));
}
static __device__ __forceinline__ void rotpairs(u64* vl, u64* vh, int stride, float2 W) {
    u64 c = pk2(W.x, W.x), s = pk2(W.y, W.y), m = pk2(-W.y, -W.y);
#pragma unroll
    for (int i = 0; i < 8; i++)
        if (!(i & stride)) {
            rp2y(vl[i], vl[i | stride], c, s, m);
            rp2y(vh[i], vh[i | stride], c, s, m);
        }
}
static __device__ __forceinline__ int swz(int e) { return e ^ (((e >> 5) & 15) << 1); }

// ---------------------------------------------------------------------------
// H tile: RYs on global bits 10..17 (wires 0..7) + deferred phase (layers 0,1).
static __device__ __forceinline__ void h_tile(
    u64* sm, const float* __restrict__ in_re, const float* __restrict__ in_im,
    int layer, int b, int chunk)
{
    const int t = threadIdx.x, lane = t & 31, wrp = t >> 5;
    const size_t base = (size_t)b * DIM;

    if (layer == 0) {
#pragma unroll
        for (int i = 0; i < 4; i++) {
            int e4 = (i * THREADS + t) * 4;
            int a = (e4 & 31) | (chunk << 5) | ((e4 >> 5) << 10);
            float4 r4 = *(const float4*)(in_re + base + a);
            float4 i4 = *(const float4*)(in_im + base + a);
            int s0 = swz(e4);
            u64x2 p0; p0.x = pk2(r4.x, i4.x); p0.y = pk2(r4.y, i4.y);
            u64x2 p1; p1.x = pk2(r4.z, i4.z); p1.y = pk2(r4.w, i4.w);
            *(u64x2*)&sm[s0]     = p0;
            *(u64x2*)&sm[s0 ^ 2] = p1;
        }
    } else {
#pragma unroll
        for (int i = 0; i < 8; i++) {
            int e = (i * THREADS + t) * 2;
            int a = (e & 31) | (chunk << 5) | ((e >> 5) << 10);
            *(u64x2*)&sm[swz(e)] = *(const u64x2*)&g_b[base + a];
        }
    }
    __syncthreads();

    u64 vl[8], vh[8];
#pragma unroll
    for (int r = 0; r < 8; r++) {
        u64x2 p = *(u64x2*)&sm[swz((wrp << 1) | (lane << 5) | (r << 10))];
        vl[r] = p.x; vh[r] = p.y;
    }
#pragma unroll
    for (int q = 0; q < 5; q++) {
        float2 W = g_ry[layer][7 - q];
        float sgn = ((lane >> q) & 1) ? W.y : -W.y;
        u64 cy2 = pk2(W.x, W.x), sgn2 = pk2(sgn, sgn);
#pragma unroll
        for (int r = 0; r < 8; r++) { shroty(vl[r], cy2, sgn2, 1 << q); shroty(vh[r], cy2, sgn2, 1 << q); }
    }
    rotpairs(vl, vh, 1, g_ry[layer][2]);
    rotpairs(vl, vh, 2, g_ry[layer][1]);
    rotpairs(vl, vh, 4, g_ry[layer][0]);
    if (layer != 2) {
#pragma unroll
        for (int r = 0; r < 8; r++) {
            u64 ph = g_phz_h[layer][lane | (r << 5)];
            vl[r] = cmulp(vl[r], ph); vh[r] = cmulp(vh[r], ph);
        }
    }
#pragma unroll
    for (int r = 0; r < 8; r++) {
        u64x2 p; p.x = vl[r]; p.y = vh[r];
        *(u64x2*)&sm[swz((wrp << 1) | (lane << 5) | (r << 10))] = p;
    }
    __syncthreads();

#pragma unroll
    for (int i = 0; i < 8; i++) {
        int e = (i * THREADS + t) * 2;
        u64x2 p = *(u64x2*)&sm[swz(e)];
        int a = (e & 31) | (chunk << 5) | ((e >> 5) << 10);
        *(u64x2*)&g_a[base + a] = p;
    }
}

// ---------------------------------------------------------------------------
// L tile: RYs on global bits 0..9 (wires 17..8) + deferred phase; write-side
// S_L permutation (quad gather) or fused exp-val on the last stage.
static __device__ __forceinline__ void l_tile(u64* sm, int layer, int last, int b, int chunk)
{
    const int t = threadIdx.x, lane = t & 31, wrp = t >> 5;
    const size_t base = (size_t)b * DIM;

    u64 vl[8], vh[8];
#pragma unroll
    for (int r = 0; r < 8; r++) {
        int e = (wrp << 9) | (r << 6) | (lane << 1);
        int a = (chunk << 13) | e;
        a ^= (a >> 1) & 0x1F000;
        u64x2 p = *(const u64x2*)&g_a[base + a];
        vl[r] = p.x; vh[r] = p.y;
    }
    {
        float2 W = g_ry[layer][17];
        u64 c = pk2(W.x, W.x), s = pk2(W.y, W.y), m = pk2(-W.y, -W.y);
#pragma unroll
        for (int r = 0; r < 8; r++) rp2y(vl[r], vh[r], c, s, m);
    }
#pragma unroll
    for (int q = 0; q < 5; q++) {
        float2 W = g_ry[layer][16 - q];
        float sgn = ((lane >> q) & 1) ? W.y : -W.y;
        u64 cy2 = pk2(W.x, W.x), sgn2 = pk2(sgn, sgn);
#pragma unroll
        for (int r = 0; r < 8; r++) { shroty(vl[r], cy2, sgn2, 1 << q); shroty(vh[r], cy2, sgn2, 1 << q); }
    }
    rotpairs(vl, vh, 1, g_ry[layer][11]);
    rotpairs(vl, vh, 2, g_ry[layer][10]);
    rotpairs(vl, vh, 4, g_ry[layer][9]);
#pragma unroll
    for (int r = 0; r < 8; r++) {
        u64x2 p; p.x = vl[r]; p.y = vh[r];
        *(u64x2*)&sm[(wrp << 9) | (r << 6) | (lane << 1)] = p;
    }
    __syncthreads();

    float2 W8 = g_ry[layer][8];
    const u64 c8 = pk2(W8.x, W8.x), s8 = pk2(W8.y, W8.y), m8 = pk2(-W8.y, -W8.y);

    if (!last) {
#pragma unroll
        for (int u = 0; u < 4; u++) {
            int j  = (lane << 1) | (u << 6) | ((wrp & 1) << 8) | ((wrp >> 1) << 10);
            int k0 = j ^ ((j >> 1) & 0xFFF);
            int sw = k0 & 1;
            int bA = k0 & ~513;
            u64x2 pA = *(u64x2*)&sm[bA];
            u64x2 pB = *(u64x2*)&sm[bA | 512];
            u64 a0 = sw ? pA.y : pA.x, a1 = sw ? pA.x : pA.y;
            u64 b0v = sw ? pB.y : pB.x, b1 = sw ? pB.x : pB.y;
            rp2y(a0, b0v, c8, s8, m8);
            rp2y(a1, b1, c8, s8, m8);
            int hi9 = k0 & 512;
            u64 f00 = hi9 ? b0v : a0;
            u64 f01 = hi9 ? b1 : a1;
            u64 f10 = hi9 ? a0 : b0v;
            u64 f11 = hi9 ? a1 : b1;
            int kx = k0 & 1023;
            u64x2 W1, W2;
            W1.x = cmulp(f00, g_phz_l[layer][kx]);
            W1.y = cmulp(f01, g_phz_l[layer][kx ^ 1]);
            W2.x = cmulp(f11, g_phz_l[layer][kx ^ 513]);
            W2.y = cmulp(f10, g_phz_l[layer][kx ^ 512]);
            *(u64x2*)&g_b[base + (size_t)((chunk << 13) | j)] = W1;
            *(u64x2*)&g_b[base + (size_t)((chunk << 13) | (j ^ 0x3FE))] = W2;
        }
    } else {
        u64 wl[8], wh[8];
        const int e2b = (lane << 1) | ((wrp & 7) << 6) | ((wrp >> 3) << 10);
#pragma unroll
        for (int r = 0; r < 8; r++) {
            int e2 = e2b | ((r & 1) << 9) | (((r >> 1) & 1) << 11) | (((r >> 2) & 1) << 12);
            u64x2 p = *(u64x2*)&sm[e2];
            wl[r] = p.x; wh[r] = p.y;
        }
#pragma unroll
        for (int i = 0; i < 8; i += 2) { rp2y(wl[i], wl[i | 1], c8, s8, m8); rp2y(wh[i], wh[i | 1], c8, s8, m8); }

        float acc[NACC];
#pragma unroll
        for (int i = 0; i < NACC; i++) acc[i] = 0.f;
#pragma unroll
        for (int r = 0; r < 8; r++) {
            int e2 = e2b | ((r & 1) << 9) | (((r >> 1) & 1) << 11) | (((r >> 2) & 1) << 12);
            float lx, ly, hx, hy;
            up2(wl[r], lx, ly); up2(wh[r], hx, hy);
            float prl = lx * lx + ly * ly;
            float prh = hx * hx + hy * hy;
            float sum = prl + prh, dif = prl - prh;
            int p = e2;
            p ^= p >> 1; p ^= p >> 2; p ^= p >> 4; p ^= p >> 8;
            acc[0] += (p & 1) ? -dif : dif;
#pragma unroll
            for (int k = 1; k < 13; k++)
                acc[k] += ((p >> k) & 1) ? -sum : sum;
            acc[13] += sum;
        }
#pragma unroll
        for (int i = 0; i < NACC; i++)
#pragma unroll
            for (int o = 16; o > 0; o >>= 1)
                acc[i] += __shfl_xor_sync(0xffffffffu, acc[i], o);
        __syncthreads();
        float* red = (float*)sm;
        if (lane == 0)
#pragma unroll
            for (int i = 0; i < NACC; i++) red[wrp * NACC + i] = acc[i];
        __syncthreads();
        if (t < NACC) {
            float s = 0.f;
            for (int w2 = 0; w2 < 16; w2++) s += red[w2 * NACC + t];
            g_part[(b * 32 + chunk) * NACC + t] = s;
        }
    }
}

// ---------------------------------------------------------------------------
// Persistent work-stealing pipeline, STAGE-MAJOR: all 2048 tiles of stage s
// (ascending batch) before stage s+1. Only ~PGRID CTAs spill across each of
// the 5 stage boundaries, and they wait on the earliest-finished batches of
// the previous stage -> soft, mostly-free boundaries instead of hard
// barriers; ramp-down of stage s overlaps ramp-up of stage s+1.
__global__ __launch_bounds__(THREADS, 2)
void circuit_kernel(const float* __restrict__ in_re, const float* __restrict__ in_im) {
    extern __shared__ u64 sm[];
    __shared__ int s_task;

    for (;;) {
        if (threadIdx.x == 0) s_task = atomicAdd(&g_qhead, 1);
        __syncthreads();
        const int i = s_task;
        if (i >= NTASK) return;

        const int s     = i / TPS;           // stage (h0,l0,h1,l1,h2,l2)
        const int j     = i - s * TPS;
        const int b     = j >> 5;            // ascending batch within stage
        const int chunk = j & 31;
        const int layer = s >> 1;

        if (threadIdx.x == 0 && s > 0) {
            while (atomicAdd(&g_done[b][s - 1], 0) < 32) __nanosleep(64);
            __threadfence();                 // acquire: order tile reads after flag
        }
        __syncthreads();

        if (!(s & 1)) h_tile(sm, in_re, in_im, layer, b, chunk);
        else          l_tile(sm, layer, s == 5, b, chunk);
        __syncthreads();

        if (threadIdx.x == 0) {
            __threadfence();                 // release: publish tile writes
            atomicAdd(&g_done[b][s], 1);
        }
    }
}

// ---------------------------------------------------------------------------
__global__ void head_kernel(const float* __restrict__ head_w,
                            const float* __restrict__ head_b,
                            float* __restrict__ out) {
    int b = threadIdx.x;
    if (b >= BATCH) return;
    float fw[NW];
#pragma unroll
    for (int w = 0; w < NW; w++) fw[w] = 0.f;
    for (int c = 0; c < 32; c++) {
        const float* pp = &g_part[(b * 32 + c) * NACC];
#pragma unroll
        for (int k = 0; k < 13; k++) fw[17 - k] += pp[k];
        float sp = pp[13];
#pragma unroll
        for (int k = 13; k < 18; k++)
            fw[17 - k] += ((c >> (k - 13)) & 1) ? -sp : sp;
    }
    float o = head_b[0];
#pragma unroll
    for (int w = 0; w < NW; w++) o += fw[w] * head_w[w];
    out[b] = o;
}

// ---------------------------------------------------------------------------
extern "C" void kernel_launch(void* const* d_in, const int* in_sizes, int n_in,
                              void* d_out, int out_size) {
    const float* state_re = (const float*)d_in[0];
    const float* state_im = (const float*)d_in[1];
    const float* params   = (const float*)d_in[2];
    const float* head_w   = (const float*)d_in[3];
    const float* head_b   = (const float*)d_in[4];
    float* out = (float*)d_out;

    const int smem = TILE * sizeof(u64);   // 64 KB
    cudaFuncSetAttribute(circuit_kernel, cudaFuncAttributeMaxDynamicSharedMemorySize, smem);

    prep_kernel<<<1, 1024>>>(params);
    circuit_kernel<<<PGRID, THREADS, smem>>>(state_re, state_im);
    head_kernel<<<1, BATCH>>>(head_w, head_b, out);
}

// round 15
// speedup vs baseline: 1.2956x; 1.0879x over previous
#include <cuda_runtime.h>

#define NW      18
#define DIM     (1 << 18)
#define BATCH   64
#define THREADS 512
#define TILE    8192           // amplitudes per CTA (u64 re/im pair -> 64 KB smem)
#define NACC    14             // 13 masked sums (bits 0..12) + total prob
#define NSTAGE  6              // h0,l0,h1,l1,h2,l2

typedef unsigned long long u64;
typedef ulonglong2 u64x2;

// Ping-pong state buffers. h: reads input/g_b, writes g_a. l: reads g_a,
// writes g_b (S_L-permuted at write) or fused exp-val on the last stage.
__device__ __align__(16) u64 g_a[(size_t)BATCH * DIM];
__device__ __align__(16) u64 g_b[(size_t)BATCH * DIM];
__device__ float2 g_ry[3][NW];
__device__ u64    g_phz_h[3][256];
__device__ u64    g_phz_l[3][1024];
__device__ float  g_part[BATCH * 32 * NACC];
__device__ int    g_done[BATCH][NSTAGE];    // per-(b,stage) completed-chunk counts

// PDL: let the next kernel in the stream start launching its CTAs now.
static __device__ __forceinline__ void pdl_trigger() {
    asm volatile("griddepcontrol.launch_dependents;" ::: "memory");
}

// ---- packed f32x2 helpers ---------------------------------------------------
static __device__ __forceinline__ u64 pk2(float x, float y) {
    u64 r; asm("mov.b64 %0,{%1,%2};" : "=l"(r) : "f"(x), "f"(y)); return r;
}
static __device__ __forceinline__ void up2(u64 a, float& x, float& y) {
    asm("mov.b64 {%0,%1},%2;" : "=f"(x), "=f"(y) : "l"(a));
}
static __device__ __forceinline__ u64 fma2_(u64 a, u64 b, u64 c) {
    u64 r; asm("fma.rn.f32x2 %0,%1,%2,%3;" : "=l"(r) : "l"(a), "l"(b), "l"(c)); return r;
}
static __device__ __forceinline__ u64 mul2_(u64 a, u64 b) {
    u64 r; asm("mul.rn.f32x2 %0,%1,%2;" : "=l"(r) : "l"(a), "l"(b)); return r;
}

// ---------------------------------------------------------------------------
__global__ void prep_kernel(const float* __restrict__ params) {
    int t = threadIdx.x;
    if (t < BATCH * NSTAGE) ((int*)g_done)[t] = 0;
    if (t < 3 * NW) {
        int l = t / NW, w = t % NW;
        float cy, sy;
        sincosf(0.5f * params[l * 36 + w], &sy, &cy);
        g_ry[l][w] = make_float2(cy, sy);
    }
    for (int i = t; i < 3 * 256; i += blockDim.x) {
        int l = i >> 8, idx = i & 255;
        float A = 0.f;
        for (int j = 0; j < 8; j++)
            if (!((idx >> j) & 1)) A += params[l * 36 + NW + (7 - j)];
        float s, c; sincosf(A, &s, &c);
        g_phz_h[l][idx] = pk2(c, -s);
    }
    for (int i = t; i < 3 * 1024; i += blockDim.x) {
        int l = i >> 10, idx = i & 1023;
        float A = 0.f;
        for (int j = 0; j < 10; j++)
            if (!((idx >> j) & 1)) A += params[l * 36 + NW + (17 - j)];
        float s, c; sincosf(A, &s, &c);
        g_phz_l[l][idx] = pk2(c, -s);
    }
}

// RY on a register pair (A: bit=0, B: bit=1).
static __device__ __forceinline__ void rp2y(u64& A, u64& B, u64 cy2, u64 sy2, u64 msy2) {
    u64 nA = fma2_(cy2, A, mul2_(msy2, B));
    u64 nB = fma2_(sy2, A, mul2_(cy2,  B));
    A = nA; B = nB;
}
static __device__ __forceinline__ void shroty(u64& v, u64 cy2, u64 sgn2, int d) {
    float vx, vy; up2(v, vx, vy);
    float ox = __shfl_xor_sync(0xffffffffu, vx, d);
    float oy = __shfl_xor_sync(0xffffffffu, vy, d);
    v = fma2_(cy2, v, mul2_(sgn2, pk2(ox, oy)));
}
static __device__ __forceinline__ u64 cmulp(u64 v, u64 p) {
    float x, y, pc, ps; up2(v, x, y); up2(p, pc, ps);
    return pk2(fmaf(-y, ps, x * pc), fmaf(x, ps, y * pc));
}
static __device__ __forceinline__ void rotpairs(u64* vl, u64* vh, int stride, float2 W) {
    u64 c = pk2(W.x, W.x), s = pk2(W.y, W.y), m = pk2(-W.y, -W.y);
#pragma unroll
    for (int i = 0; i < 8; i++)
        if (!(i & stride)) {
            rp2y(vl[i], vl[i | stride], c, s, m);
            rp2y(vh[i], vh[i | stride], c, s, m);
        }
}
static __device__ __forceinline__ int swz(int e) { return e ^ (((e >> 5) & 15) << 1); }

// Soft cross-kernel dependency (per batch): wait for all 32 tiles of the
// previous stage of this batch, then acquire.
static __device__ __forceinline__ void dep_wait(int b, int s) {
    if (s > 0) {
        if (threadIdx.x == 0) {
            while (atomicAdd(&g_done[b][s - 1], 0) < 32) __nanosleep(64);
            __threadfence();
        }
        __syncthreads();
    }
}
static __device__ __forceinline__ void dep_publish(int b, int s) {
    __syncthreads();
    if (threadIdx.x == 0) {
        __threadfence();
        atomicAdd(&g_done[b][s], 1);
    }
}

// ---------------------------------------------------------------------------
// H kernel: RYs on global bits 10..17 (wires 0..7) + one deferred phase.
// Tile bits {0..4} u {10..17}; chunk = bits 5..9. g_b already holds the
// S_L-permuted state -> plain contiguous read.
__global__ __launch_bounds__(THREADS, 2)
void h_kernel(const float* __restrict__ in_re, const float* __restrict__ in_im,
              int layer, int stage) {
    extern __shared__ u64 sm[];
    const int t = threadIdx.x, lane = t & 31, wrp = t >> 5;
    const int b = blockIdx.x >> 5, chunk = blockIdx.x & 31;
    const size_t base = (size_t)b * DIM;

    pdl_trigger();
    dep_wait(b, stage);

    if (layer == 0) {
#pragma unroll
        for (int i = 0; i < 4; i++) {
            int e4 = (i * THREADS + t) * 4;
            int a = (e4 & 31) | (chunk << 5) | ((e4 >> 5) << 10);
            float4 r4 = *(const float4*)(in_re + base + a);
            float4 i4 = *(const float4*)(in_im + base + a);
            int s0 = swz(e4);
            u64x2 p0; p0.x = pk2(r4.x, i4.x); p0.y = pk2(r4.y, i4.y);
            u64x2 p1; p1.x = pk2(r4.z, i4.z); p1.y = pk2(r4.w, i4.w);
            *(u64x2*)&sm[s0]     = p0;
            *(u64x2*)&sm[s0 ^ 2] = p1;
        }
    } else {
#pragma unroll
        for (int i = 0; i < 8; i++) {
            int e = (i * THREADS + t) * 2;
            int a = (e & 31) | (chunk << 5) | ((e >> 5) << 10);
            *(u64x2*)&sm[swz(e)] = *(const u64x2*)&g_b[base + a];
        }
    }
    __syncthreads();

    u64 vl[8], vh[8];
#pragma unroll
    for (int r = 0; r < 8; r++) {
        u64x2 p = *(u64x2*)&sm[swz((wrp << 1) | (lane << 5) | (r << 10))];
        vl[r] = p.x; vh[r] = p.y;
    }
#pragma unroll
    for (int q = 0; q < 5; q++) {
        float2 W = g_ry[layer][7 - q];
        float sgn = ((lane >> q) & 1) ? W.y : -W.y;
        u64 cy2 = pk2(W.x, W.x), sgn2 = pk2(sgn, sgn);
#pragma unroll
        for (int r = 0; r < 8; r++) { shroty(vl[r], cy2, sgn2, 1 << q); shroty(vh[r], cy2, sgn2, 1 << q); }
    }
    rotpairs(vl, vh, 1, g_ry[layer][2]);
    rotpairs(vl, vh, 2, g_ry[layer][1]);
    rotpairs(vl, vh, 4, g_ry[layer][0]);
    if (layer != 2) {
#pragma unroll
        for (int r = 0; r < 8; r++) {
            u64 ph = g_phz_h[layer][lane | (r << 5)];
            vl[r] = cmulp(vl[r], ph); vh[r] = cmulp(vh[r], ph);
        }
    }
#pragma unroll
    for (int r = 0; r < 8; r++) {
        u64x2 p; p.x = vl[r]; p.y = vh[r];
        *(u64x2*)&sm[swz((wrp << 1) | (lane << 5) | (r << 10))] = p;
    }
    __syncthreads();

#pragma unroll
    for (int i = 0; i < 8; i++) {
        int e = (i * THREADS + t) * 2;
        u64x2 p = *(u64x2*)&sm[swz(e)];
        int a = (e & 31) | (chunk << 5) | ((e >> 5) << 10);
        *(u64x2*)&g_a[base + a] = p;
    }

    dep_publish(b, stage);
}

// ---------------------------------------------------------------------------
// L kernel: RYs on global bits 0..9 (wires 17..8) + one deferred phase.
// Tile = contiguous bits 0..12; chunk = bits 13..17 (ASCENDING order so the
// consumer's wait order matches the producer's completion order under PDL
// overlap). Read folds this layer's high chain segment. Write side applies
// the S_L permutation (quad gather) -> contiguous g_b; last stage does the
// wire-8 rotation + fused exp-val instead.
__global__ __launch_bounds__(THREADS, 2)
void l_kernel(int layer, int last, int stage) {
    extern __shared__ u64 sm[];
    const int t = threadIdx.x, lane = t & 31, wrp = t >> 5;
    const int b = blockIdx.x >> 5, chunk = blockIdx.x & 31;
    const size_t base = (size_t)b * DIM;

    pdl_trigger();
    dep_wait(b, stage);

    u64 vl[8], vh[8];
#pragma unroll
    for (int r = 0; r < 8; r++) {
        int e = (wrp << 9) | (r << 6) | (lane << 1);
        int a = (chunk << 13) | e;
        a ^= (a >> 1) & 0x1F000;
        u64x2 p = *(const u64x2*)&g_a[base + a];
        vl[r] = p.x; vh[r] = p.y;
    }
    {
        float2 W = g_ry[layer][17];
        u64 c = pk2(W.x, W.x), s = pk2(W.y, W.y), m = pk2(-W.y, -W.y);
#pragma unroll
        for (int r = 0; r < 8; r++) rp2y(vl[r], vh[r], c, s, m);
    }
#pragma unroll
    for (int q = 0; q < 5; q++) {
        float2 W = g_ry[layer][16 - q];
        float sgn = ((lane >> q) & 1) ? W.y : -W.y;
        u64 cy2 = pk2(W.x, W.x), sgn2 = pk2(sgn, sgn);
#pragma unroll
        for (int r = 0; r < 8; r++) { shroty(vl[r], cy2, sgn2, 1 << q); shroty(vh[r], cy2, sgn2, 1 << q); }
    }
    rotpairs(vl, vh, 1, g_ry[layer][11]);
    rotpairs(vl, vh, 2, g_ry[layer][10]);
    rotpairs(vl, vh, 4, g_ry[layer][9]);
#pragma unroll
    for (int r = 0; r < 8; r++) {
        u64x2 p; p.x = vl[r]; p.y = vh[r];
        *(u64x2*)&sm[(wrp << 9) | (r << 6) | (lane << 1)] = p;
    }
    __syncthreads();

    float2 W8 = g_ry[layer][8];
    const u64 c8 = pk2(W8.x, W8.x), s8 = pk2(W8.y, W8.y), m8 = pk2(-W8.y, -W8.y);

    if (!last) {
#pragma unroll
        for (int u = 0; u < 4; u++) {
            int j  = (lane << 1) | (u << 6) | ((wrp & 1) << 8) | ((wrp >> 1) << 10);
            int k0 = j ^ ((j >> 1) & 0xFFF);
            int sw = k0 & 1;
            int bA = k0 & ~513;
            u64x2 pA = *(u64x2*)&sm[bA];
            u64x2 pB = *(u64x2*)&sm[bA | 512];
            u64 a0 = sw ? pA.y : pA.x, a1 = sw ? pA.x : pA.y;
            u64 b0v = sw ? pB.y : pB.x, b1 = sw ? pB.x : pB.y;
            rp2y(a0, b0v, c8, s8, m8);
            rp2y(a1, b1, c8, s8, m8);
            int hi9 = k0 & 512;
            u64 f00 = hi9 ? b0v : a0;
            u64 f01 = hi9 ? b1 : a1;
            u64 f10 = hi9 ? a0 : b0v;
            u64 f11 = hi9 ? a1 : b1;
            int kx = k0 & 1023;
            u64x2 W1, W2;
            W1.x = cmulp(f00, g_phz_l[layer][kx]);
            W1.y = cmulp(f01, g_phz_l[layer][kx ^ 1]);
            W2.x = cmulp(f11, g_phz_l[layer][kx ^ 513]);
            W2.y = cmulp(f10, g_phz_l[layer][kx ^ 512]);
            *(u64x2*)&g_b[base + (size_t)((chunk << 13) | j)] = W1;
            *(u64x2*)&g_b[base + (size_t)((chunk << 13) | (j ^ 0x3FE))] = W2;
        }
        dep_publish(b, stage);
    } else {
        u64 wl[8], wh[8];
        const int e2b = (lane << 1) | ((wrp & 7) << 6) | ((wrp >> 3) << 10);
#pragma unroll
        for (int r = 0; r < 8; r++) {
            int e2 = e2b | ((r & 1) << 9) | (((r >> 1) & 1) << 11) | (((r >> 2) & 1) << 12);
            u64x2 p = *(u64x2*)&sm[e2];
            wl[r] = p.x; wh[r] = p.y;
        }
#pragma unroll
        for (int i = 0; i < 8; i += 2) { rp2y(wl[i], wl[i | 1], c8, s8, m8); rp2y(wh[i], wh[i | 1], c8, s8, m8); }

        float acc[NACC];
#pragma unroll
        for (int i = 0; i < NACC; i++) acc[i] = 0.f;
#pragma unroll
        for (int r = 0; r < 8; r++) {
            int e2 = e2b | ((r & 1) << 9) | (((r >> 1) & 1) << 11) | (((r >> 2) & 1) << 12);
            float lx, ly, hx, hy;
            up2(wl[r], lx, ly); up2(wh[r], hx, hy);
            float prl = lx * lx + ly * ly;
            float prh = hx * hx + hy * hy;
            float sum = prl + prh, dif = prl - prh;
            int p = e2;
            p ^= p >> 1; p ^= p >> 2; p ^= p >> 4; p ^= p >> 8;
            acc[0] += (p & 1) ? -dif : dif;
#pragma unroll
            for (int k = 1; k < 13; k++)
                acc[k] += ((p >> k) & 1) ? -sum : sum;
            acc[13] += sum;
        }
#pragma unroll
        for (int i = 0; i < NACC; i++)
#pragma unroll
            for (int o = 16; o > 0; o >>= 1)
                acc[i] += __shfl_xor_sync(0xffffffffu, acc[i], o);
        __syncthreads();
        float* red = (float*)sm;
        if (lane == 0)
#pragma unroll
            for (int i = 0; i < NACC; i++) red[wrp * NACC + i] = acc[i];
        __syncthreads();
        if (t < NACC) {
            float s = 0.f;
            for (int w2 = 0; w2 < 16; w2++) s += red[w2 * NACC + t];
            g_part[(b * 32 + chunk) * NACC + t] = s;
        }
    }
}

// ---------------------------------------------------------------------------
__global__ void head_kernel(const float* __restrict__ head_w,
                            const float* __restrict__ head_b,
                            float* __restrict__ out) {
    int b = threadIdx.x;
    if (b >= BATCH) return;
    float fw[NW];
#pragma unroll
    for (int w = 0; w < NW; w++) fw[w] = 0.f;
    for (int c = 0; c < 32; c++) {
        const float* pp = &g_part[(b * 32 + c) * NACC];
#pragma unroll
        for (int k = 0; k < 13; k++) fw[17 - k] += pp[k];
        float sp = pp[13];
#pragma unroll
        for (int k = 13; k < 18; k++)
            fw[17 - k] += ((c >> (k - 13)) & 1) ? -sp : sp;
    }
    float o = head_b[0];
#pragma unroll
    for (int w = 0; w < NW; w++) o += fw[w] * head_w[w];
    out[b] = o;
}

// ---------------------------------------------------------------------------
extern "C" void kernel_launch(void* const* d_in, const int* in_sizes, int n_in,
                              void* d_out, int out_size) {
    const float* state_re = (const float*)d_in[0];
    const float* state_im = (const float*)d_in[1];
    const float* params   = (const float*)d_in[2];
    const float* head_w   = (const float*)d_in[3];
    const float* head_b   = (const float*)d_in[4];
    float* out = (float*)d_out;

    const size_t smem = TILE * sizeof(u64);   // 64 KB
    cudaFuncSetAttribute(h_kernel, cudaFuncAttributeMaxDynamicSharedMemorySize, (int)smem);
    cudaFuncSetAttribute(l_kernel, cudaFuncAttributeMaxDynamicSharedMemorySize, (int)smem);

    prep_kernel<<<1, 1024>>>(params);

    // PDL pipeline: each stage kernel triggers launch_dependents at entry, so
    // the next stage's CTAs fill SM slots as this stage's last wave drains.
    // Per-batch soft flags carry the actual data dependency.
    cudaLaunchAttribute attr[1];
    attr[0].id = cudaLaunchAttributeProgrammaticStreamSerialization;
    attr[0].val.programmaticStreamSerializationAllowed = 1;

    cudaLaunchConfig_t cfg = {};
    cfg.gridDim = dim3(BATCH * 32);
    cfg.blockDim = dim3(THREADS);
    cfg.dynamicSmemBytes = smem;
    cfg.stream = 0;
    cfg.attrs = attr;
    cfg.numAttrs = 1;

    for (int l = 0; l < 3; l++) {
        if (l == 0) {
            // First stage: no PDL attr (prep never triggers; keep default
            // full-completion dependency on prep).
            h_kernel<<<BATCH * 32, THREADS, smem>>>(state_re, state_im, 0, 0);
        } else {
            cudaLaunchKernelEx(&cfg, h_kernel, state_re, state_im, l, 2 * l);
        }
        cudaLaunchKernelEx(&cfg, l_kernel, l, (int)(l == 2), 2 * l + 1);
    }

    // head: normal launch -> waits for l2 to fully complete.
    head_kernel<<<1, BATCH>>>(head_w, head_b, out);
}